// round 9
// baseline (speedup 1.0000x reference)
#include <cuda_runtime.h>
#include <cuda_bf16.h>

// FM layer: out[b,:] = 0.5 * ((sum v*e)^2 - sum (v*e)^2), batch_ids sorted.
// Two kernels overlapped via Programmatic Dependent Launch:
//   1) boundary_kernel: sorted batch_ids -> CSR row starts (16 elems/thread,
//      exactly-once, no atomics). Triggers programmatic completion early.
//   2) fm_main: proven gather body (38.4us standalone); launched with
//      programmatic stream serialization, syncs on the grid dependency
//      before reading g_starts. Launch latency + CTA ramp overlap kernel 1.
//
// Inputs:
//   d_in[0] feature_embedding float32 [1e6, 64]
//   d_in[1] feature_vals      float32 [819200]
//   d_in[2] batch_ids         int32   [819200] sorted
//   d_in[3] feat_ids          int32   [819200]
//   d_in[4] batch_size        int32   [1]
// Output float32 [4096, 64]

#define EMBED  64
#define GROUPS 8              // 8 warps per CTA, group-strided over the segment
#define BLOCK  256
#define EPT    16             // boundary kernel: elements per thread

__device__ int g_starts[4097];

__global__ void boundary_kernel(const int* __restrict__ bids, int nnz, int batch)
{
    int base = EPT * (blockIdx.x * blockDim.x + threadIdx.x);
    if (base < nnz) {
        int prev = (base == 0) ? -1 : __ldg(bids + base - 1);

        if (base + EPT <= nnz) {
            // fast path: 4 independent int4 loads in flight
            int4 c0 = __ldg((const int4*)(bids + base));
            int4 c1 = __ldg((const int4*)(bids + base + 4));
            int4 c2 = __ldg((const int4*)(bids + base + 8));
            int4 c3 = __ldg((const int4*)(bids + base + 12));
            int cs[EPT] = {c0.x, c0.y, c0.z, c0.w,
                           c1.x, c1.y, c1.z, c1.w,
                           c2.x, c2.y, c2.z, c2.w,
                           c3.x, c3.y, c3.z, c3.w};
            #pragma unroll
            for (int k = 0; k < EPT; k++) {
                for (int b = prev + 1; b <= cs[k]; b++) g_starts[b] = base + k;
                prev = cs[k];
            }
            if (base + EPT == nnz) {
                for (int b = prev + 1; b <= batch; b++) g_starts[b] = nnz;
            }
        } else {
            for (int k = 0; k < EPT; k++) {
                int p = base + k;
                if (p >= nnz) { for (int b = prev + 1; b <= batch; b++) g_starts[b] = nnz; break; }
                int cur = __ldg(bids + p);
                for (int b = prev + 1; b <= cur; b++) g_starts[b] = p;
                prev = cur;
            }
        }
    }
    // signal the dependent kernel that our stores are on the way out
    cudaTriggerProgrammaticLaunchCompletion();
}

__global__ __launch_bounds__(BLOCK, 8)
void fm_main(const float* __restrict__ emb,
             const float* __restrict__ vals,
             const int*   __restrict__ fids,
             float*       __restrict__ out)
{
    const int b = blockIdx.x;
    const int t = threadIdx.x & 31;     // float2 lane: dims [2t, 2t+1]
    const int g = threadIdx.x >> 5;     // warp/group 0..7

    // wait until boundary_kernel's writes to g_starts are visible
    cudaGridDependencySynchronize();

    const int lo = g_starts[b];
    const int hi = g_starts[b + 1];

    const float2* __restrict__ emb2 = (const float2*)emb;

    float sx = 0.f, sy = 0.f, qx = 0.f, qy = 0.f;

    int i = lo + g;
    // 4-deep gather pipeline per thread
    for (; i + 3 * GROUPS < hi; i += 4 * GROUPS) {
        int f0 = __ldg(fids + i);
        int f1 = __ldg(fids + i +     GROUPS);
        int f2 = __ldg(fids + i + 2 * GROUPS);
        int f3 = __ldg(fids + i + 3 * GROUPS);
        float v0 = __ldg(vals + i);
        float v1 = __ldg(vals + i +     GROUPS);
        float v2 = __ldg(vals + i + 2 * GROUPS);
        float v3 = __ldg(vals + i + 3 * GROUPS);
        float2 e0 = __ldg(emb2 + f0 * 32 + t);
        float2 e1 = __ldg(emb2 + f1 * 32 + t);
        float2 e2 = __ldg(emb2 + f2 * 32 + t);
        float2 e3 = __ldg(emb2 + f3 * 32 + t);

        float ax, ay;
        ax = v0 * e0.x; ay = v0 * e0.y; sx += ax; qx = fmaf(ax, ax, qx); sy += ay; qy = fmaf(ay, ay, qy);
        ax = v1 * e1.x; ay = v1 * e1.y; sx += ax; qx = fmaf(ax, ax, qx); sy += ay; qy = fmaf(ay, ay, qy);
        ax = v2 * e2.x; ay = v2 * e2.y; sx += ax; qx = fmaf(ax, ax, qx); sy += ay; qy = fmaf(ay, ay, qy);
        ax = v3 * e3.x; ay = v3 * e3.y; sx += ax; qx = fmaf(ax, ax, qx); sy += ay; qy = fmaf(ay, ay, qy);
    }
    for (; i < hi; i += GROUPS) {
        int   f = __ldg(fids + i);
        float v = __ldg(vals + i);
        float2 e = __ldg(emb2 + f * 32 + t);
        float ax = v * e.x, ay = v * e.y;
        sx += ax; qx = fmaf(ax, ax, qx);
        sy += ay; qy = fmaf(ay, ay, qy);
    }

    // combine 8 groups through shared memory
    __shared__ float ssx[GROUPS][32], ssy[GROUPS][32];
    __shared__ float sqx[GROUPS][32], sqy[GROUPS][32];
    ssx[g][t] = sx; ssy[g][t] = sy;
    sqx[g][t] = qx; sqy[g][t] = qy;
    __syncthreads();

    if (g == 0) {
        float Sx = sx, Sy = sy, Qx = qx, Qy = qy;
        #pragma unroll
        for (int k = 1; k < GROUPS; k++) {
            Sx += ssx[k][t]; Sy += ssy[k][t];
            Qx += sqx[k][t]; Qy += sqy[k][t];
        }
        float2 o;
        o.x = 0.5f * (Sx * Sx - Qx);
        o.y = 0.5f * (Sy * Sy - Qy);
        ((float2*)out)[b * 32 + t] = o;
    }
}

extern "C" void kernel_launch(void* const* d_in, const int* in_sizes, int n_in,
                              void* d_out, int out_size)
{
    const float* emb  = (const float*)d_in[0];
    const float* vals = (const float*)d_in[1];
    const int*   bids = (const int*)d_in[2];
    const int*   fids = (const int*)d_in[3];
    float* out = (float*)d_out;

    int nnz   = in_sizes[1];
    int batch = out_size / EMBED;   // 4096

    int bthreads = (nnz + EPT - 1) / EPT;
    boundary_kernel<<<(bthreads + 255) / 256, 256>>>(bids, nnz, batch);

    // fm_main with programmatic dependent launch: starts ramping while
    // boundary_kernel drains; gridDependencySynchronize() gates g_starts use.
    cudaLaunchAttribute attrs[1];
    attrs[0].id = cudaLaunchAttributeProgrammaticStreamSerialization;
    attrs[0].val.programmaticStreamSerializationAllowed = 1;

    cudaLaunchConfig_t cfg = {};
    cfg.gridDim  = dim3(batch);
    cfg.blockDim = dim3(BLOCK);
    cfg.dynamicSmemBytes = 0;
    cfg.stream = 0;
    cfg.attrs = attrs;
    cfg.numAttrs = 1;

    cudaLaunchKernelEx(&cfg, fm_main, emb, vals, fids, out);
}